// round 14
// baseline (speedup 1.0000x reference)
#include <cuda_runtime.h>
#include <cuda_bf16.h>
#include <cstdint>

// CTRNN: h_{t+1} = 0.8h + 0.2 tanh([h|x_t] @ [W_hh|W_in]^T + b)
// T=1000, B=256, I=128, N=512, K = 640.
//
// Round-14 delta vs round-13 (9572us, tensor=8.7%, issue=12.6%):
//  1. GEMM split terms use SEPARATE accumulators (acc0/1/2, summed in the
//     epilogue) -> 3 independent 40-deep HMMA chains instead of one 120-deep
//     RAW chain (the diagnosed dominant stall).
//  2. Fragment double-buffering: k-tile kt+1 LDSMs issue under kt's MMAs.
// Rest unchanged: mma.sync m16n8k16 bf16, 16 clusters x 8 CTAs, W hi/lo in
// smem, h|x via L2 bf16 hi/lo double buffer, cluster-barrier release/acquire.

#define T_STEPS 1000
#define BATCH 256
#define INPUT 128
#define NHID 512
#define BN (BATCH * NHID)
#define KTOT 640
#define APITCH 648            // bf16 elems per row; 1296B -> ldmatrix conflict-free

// smem byte offsets (all 16B aligned)
#define S_WH 0
#define S_WL (S_WH + 64 * APITCH * 2)     //  82944
#define S_AH (S_WL + 64 * APITCH * 2)     // 165888
#define S_AL (S_AH + 16 * APITCH * 2)     // 186624
#define S_HOLD (S_AL + 16 * APITCH * 2)   // 207360  fp32 h_old [16][64]
#define S_BIAS (S_HOLD + 16 * 64 * 4)     // 211456  fp32 [64]
#define SMEM_BYTES (S_BIAS + 256)         // 211712

__device__ __nv_bfloat16 g_hh[2][BATCH][KTOT];   // hi parts of [h | x_t]
__device__ __nv_bfloat16 g_hl[2][BATCH][KTOT];   // lo parts

__device__ __forceinline__ uint32_t smem_u32(const void* p) {
    uint32_t a;
    asm("{ .reg .u64 t; cvta.to.shared.u64 t, %1; cvt.u32.u64 %0, t; }"
        : "=r"(a) : "l"(p));
    return a;
}

__device__ __forceinline__ void cluster_arrive() {  // release @ cluster scope
    asm volatile("barrier.cluster.arrive.aligned;" ::: "memory");
}
__device__ __forceinline__ void cluster_wait() {    // acquire @ cluster scope
    asm volatile("barrier.cluster.wait.aligned;" ::: "memory");
}

__device__ __forceinline__ void ldsm4(uint32_t* r, uint32_t a) {
    asm volatile("ldmatrix.sync.aligned.m8n8.x4.shared.b16 {%0,%1,%2,%3}, [%4];"
                 : "=r"(r[0]), "=r"(r[1]), "=r"(r[2]), "=r"(r[3]) : "r"(a));
}
__device__ __forceinline__ void ldsm2(uint32_t* r, uint32_t a) {
    asm volatile("ldmatrix.sync.aligned.m8n8.x2.shared.b16 {%0,%1}, [%2];"
                 : "=r"(r[0]), "=r"(r[1]) : "r"(a));
}
__device__ __forceinline__ void mma_bf16(float* c, const uint32_t* a,
                                         const uint32_t* b) {
    asm volatile(
        "mma.sync.aligned.m16n8k16.row.col.f32.bf16.bf16.f32 "
        "{%0,%1,%2,%3}, {%4,%5,%6,%7}, {%8,%9}, {%0,%1,%2,%3};"
        : "+f"(c[0]), "+f"(c[1]), "+f"(c[2]), "+f"(c[3])
        : "r"(a[0]), "r"(a[1]), "r"(a[2]), "r"(a[3]), "r"(b[0]), "r"(b[1]));
}

__device__ __forceinline__ void split_bf16(float v, unsigned short& hi,
                                           unsigned short& lo) {
    __nv_bfloat16 h = __float2bfloat16(v);
    __nv_bfloat16 l = __float2bfloat16(v - __bfloat162float(h));
    hi = *(unsigned short*)&h;
    lo = *(unsigned short*)&l;
}

extern "C" __global__ void __launch_bounds__(256, 1) __cluster_dims__(8, 1, 1)
ctrnn_hmma(const float* __restrict__ x, const float* __restrict__ h0,
           const float* __restrict__ W_in, const float* __restrict__ b_in,
           const float* __restrict__ W_hh, float* __restrict__ out) {
    extern __shared__ char S[];
    const uint32_t sb = smem_u32(S);
    const int tid = threadIdx.x;
    const int warp = tid >> 5;          // n-strip (0..7): cols [warp*8, warp*8+8)
    const int lane = tid & 31;
    const int cid = blockIdx.x >> 3;    // cluster -> batch group (16 rows)
    const int rank = blockIdx.x & 7;    // -> column group (64 cols)
    const int rows0 = cid * 16;
    const int cols0 = rank * 64;

    // ---- one-time: W slice [64 cols x 640 k] -> smem bf16 hi/lo ----
    for (int i = tid; i < 64 * KTOT; i += 256) {
        int c = i / KTOT, k = i % KTOT;
        int gn = cols0 + c;
        float w = (k < NHID) ? W_hh[gn * NHID + k] : W_in[gn * INPUT + (k - NHID)];
        unsigned short hi, lo;
        split_bf16(w, hi, lo);
        *(unsigned short*)(S + S_WH + (c * APITCH + k) * 2) = hi;
        *(unsigned short*)(S + S_WL + (c * APITCH + k) * 2) = lo;
    }
    if (tid < 64) ((float*)(S + S_BIAS))[tid] = b_in[cols0 + tid];

    // ---- h0 -> h_old smem + exchange[0] (this CTA's 16x64 tile) ----
    {
        int r = tid >> 4, c = 4 * (tid & 15);
        float4 v = *(const float4*)&h0[(rows0 + r) * NHID + cols0 + c];
        float* hold = (float*)(S + S_HOLD);
        *(float4*)&hold[r * 64 + c] = v;
        unsigned short hh[4], hl[4];
        split_bf16(v.x, hh[0], hl[0]); split_bf16(v.y, hh[1], hl[1]);
        split_bf16(v.z, hh[2], hl[2]); split_bf16(v.w, hh[3], hl[3]);
        *(unsigned long long*)&g_hh[0][rows0 + r][cols0 + c] = *(unsigned long long*)hh;
        *(unsigned long long*)&g_hl[0][rows0 + r][cols0 + c] = *(unsigned long long*)hl;
    }
    // x_0: this CTA covers 16 rows x 16 x-cols
    {
        int r = tid >> 4, xc = tid & 15;
        float v = x[(rows0 + r) * INPUT + rank * 16 + xc];
        unsigned short hi, lo;
        split_bf16(v, hi, lo);
        *(unsigned short*)&g_hh[0][rows0 + r][NHID + rank * 16 + xc] = hi;
        *(unsigned short*)&g_hl[0][rows0 + r][NHID + rank * 16 + xc] = lo;
    }
    cluster_arrive();
    cluster_wait();

    // ---- ldmatrix lane address bases ----
    const int arow = lane & 15;
    const int akoff = (lane >> 4) ? 8 : 0;
    const uint32_t aH = sb + S_AH + (uint32_t)(arow * APITCH + akoff) * 2;
    const uint32_t aL = sb + S_AL + (uint32_t)(arow * APITCH + akoff) * 2;
    const int bcol = warp * 8 + (lane & 7);
    const int bkoff = ((lane >> 3) & 1) ? 8 : 0;
    const uint32_t bH = sb + S_WH + (uint32_t)(bcol * APITCH + bkoff) * 2;
    const uint32_t bL = sb + S_WL + (uint32_t)(bcol * APITCH + bkoff) * 2;

    int p = 0;
    for (int t = 0; t < T_STEPS; t++) {
        // ---- stage A [16 x 640] hi/lo from L2 exchange into padded smem ----
        {
            int r = tid >> 4, seg = tid & 15;           // 40 cols = 80B per seg
            const uint4* srcH = (const uint4*)&g_hh[p][rows0 + r][seg * 40];
            const uint4* srcL = (const uint4*)&g_hl[p][rows0 + r][seg * 40];
            uint4* dstH = (uint4*)(S + S_AH + (r * APITCH + seg * 40) * 2);
            uint4* dstL = (uint4*)(S + S_AL + (r * APITCH + seg * 40) * 2);
#pragma unroll
            for (int j = 0; j < 5; j++) { dstH[j] = __ldcg(srcH + j); }
#pragma unroll
            for (int j = 0; j < 5; j++) { dstL[j] = __ldcg(srcL + j); }
        }
        // x_{t+1} prefetch (scalar; drains during GEMM)
        float xr = 0.0f;
        if (t + 1 < T_STEPS)
            xr = __ldcs(&x[(size_t)(t + 1) * BATCH * INPUT +
                           (size_t)(rows0 + (tid >> 4)) * INPUT + rank * 16 + (tid & 15)]);
        __syncthreads();

        // ---- GEMM: 40 k-tiles, 3 split terms with INDEPENDENT accumulators,
        //      fragments double-buffered (kt+1 LDSMs under kt MMAs) ----
        float acc0[4] = {0.f, 0.f, 0.f, 0.f};
        float acc1[4] = {0.f, 0.f, 0.f, 0.f};
        float acc2[4] = {0.f, 0.f, 0.f, 0.f};
        uint32_t ah[2][4], al[2][4], bh[2][2], bl[2][2];
        ldsm4(ah[0], aH);
        ldsm4(al[0], aL);
        ldsm2(bh[0], bH);
        ldsm2(bl[0], bL);
#pragma unroll 4
        for (int kt = 0; kt < 40; kt++) {
            int cur = kt & 1, nxt = cur ^ 1;
            if (kt < 39) {
                uint32_t ko = (uint32_t)(kt + 1) * 32;   // 16 bf16 = 32B per tile
                ldsm4(ah[nxt], aH + ko);
                ldsm4(al[nxt], aL + ko);
                ldsm2(bh[nxt], bH + ko);
                ldsm2(bl[nxt], bL + ko);
            }
            mma_bf16(acc0, ah[cur], bh[cur]);
            mma_bf16(acc1, ah[cur], bl[cur]);
            mma_bf16(acc2, al[cur], bh[cur]);
        }
#pragma unroll
        for (int j = 0; j < 4; j++) acc0[j] += acc1[j] + acc2[j];

        // ---- epilogue: frag (r, r+8) x (n, n+1); bias+tanh+blend ----
        const int r0 = lane >> 2;
        const int n = warp * 8 + 2 * (lane & 3);
        float* hold = (float*)(S + S_HOLD);
        const float* bs = (const float*)(S + S_BIAS);
        float b0 = bs[n], b1 = bs[n + 1];
        float h00 = hold[r0 * 64 + n],       h01 = hold[r0 * 64 + n + 1];
        float h10 = hold[(r0 + 8) * 64 + n], h11 = hold[(r0 + 8) * 64 + n + 1];
        float v00 = h00 * 0.8f + 0.2f * tanhf(acc0[0] + b0);
        float v01 = h01 * 0.8f + 0.2f * tanhf(acc0[1] + b1);
        float v10 = h10 * 0.8f + 0.2f * tanhf(acc0[2] + b0);
        float v11 = h11 * 0.8f + 0.2f * tanhf(acc0[3] + b1);
        hold[r0 * 64 + n] = v00;       hold[r0 * 64 + n + 1] = v01;
        hold[(r0 + 8) * 64 + n] = v10; hold[(r0 + 8) * 64 + n + 1] = v11;

        // publish h_{t+1} hi/lo (bf16x2 per row-pair of cols)
        unsigned short s00h, s00l, s01h, s01l, s10h, s10l, s11h, s11l;
        split_bf16(v00, s00h, s00l); split_bf16(v01, s01h, s01l);
        split_bf16(v10, s10h, s10l); split_bf16(v11, s11h, s11l);
        *(uint32_t*)&g_hh[p ^ 1][rows0 + r0][cols0 + n] =
            (uint32_t)s00h | ((uint32_t)s01h << 16);
        *(uint32_t*)&g_hl[p ^ 1][rows0 + r0][cols0 + n] =
            (uint32_t)s00l | ((uint32_t)s01l << 16);
        *(uint32_t*)&g_hh[p ^ 1][rows0 + r0 + 8][cols0 + n] =
            (uint32_t)s10h | ((uint32_t)s11h << 16);
        *(uint32_t*)&g_hl[p ^ 1][rows0 + r0 + 8][cols0 + n] =
            (uint32_t)s10l | ((uint32_t)s11l << 16);
        // publish x_{t+1}
        if (t + 1 < T_STEPS) {
            unsigned short xh, xl;
            split_bf16(xr, xh, xl);
            *(unsigned short*)&g_hh[p ^ 1][rows0 + (tid >> 4)][NHID + rank * 16 + (tid & 15)] = xh;
            *(unsigned short*)&g_hl[p ^ 1][rows0 + (tid >> 4)][NHID + rank * 16 + (tid & 15)] = xl;
        }

        // release exchange stores; hide output stores inside the barrier
        cluster_arrive();
        {
            size_t ob = (size_t)t * BN + (size_t)(rows0 + r0) * NHID + cols0 + n;
            size_t ob8 = ob + 8 * NHID;
            *(float2*)&out[ob] = make_float2(v00, v01);
            *(float2*)&out[ob8] = make_float2(v10, v11);
            if (t == T_STEPS - 1) {
                *(float2*)&out[ob + (size_t)T_STEPS * BN - (size_t)t * BN] =
                    make_float2(v00, v01);
                *(float2*)&out[ob8 + (size_t)T_STEPS * BN - (size_t)t * BN] =
                    make_float2(v10, v11);
            }
        }
        cluster_wait();
        p ^= 1;
    }
}

extern "C" void kernel_launch(void* const* d_in, const int* in_sizes, int n_in,
                              void* d_out, int out_size) {
    const float* x    = (const float*)d_in[0];
    const float* h0   = (const float*)d_in[1];
    const float* W_in = (const float*)d_in[2];
    const float* b_in = (const float*)d_in[3];
    const float* W_hh = (const float*)d_in[4];
    float* out = (float*)d_out;

    cudaFuncSetAttribute(ctrnn_hmma,
                         cudaFuncAttributeMaxDynamicSharedMemorySize, SMEM_BYTES);
    ctrnn_hmma<<<128, 256, SMEM_BYTES>>>(x, h0, W_in, b_in, W_hh, out);
}